// round 2
// baseline (speedup 1.0000x reference)
#include <cuda_runtime.h>
#include <cuda_bf16.h>

#define FULL_MASK 0xFFFFFFFFu

// 4 segments per row -> 1024 blocks: wave imbalance drops from 1.16x to 1.01x.
#define SEGS   4
#define BROWS  256
#define NBLK   (BROWS * SEGS)

// Cross-segment parity handoff (decoupled lookback). bit1 = ready, bit0 = parity.
__device__ int g_flags[NBLK];

__global__ void init_flags_kernel() { g_flags[threadIdx.x] = 0; }

static __device__ __forceinline__ float fast_sqrt(float x) {
    float y;
    asm("sqrt.approx.f32 %0, %1;" : "=f"(y) : "f"(x));
    return y;
}

static __device__ __forceinline__ void publish_flag(int* p, int v) {
    asm volatile("st.global.release.gpu.b32 [%0], %1;" :: "l"(p), "r"(v) : "memory");
}

static __device__ __forceinline__ int read_flag(const int* p) {
    int v;
    asm volatile("ld.global.acquire.gpu.b32 %0, [%1];" : "=r"(v) : "l"(p) : "memory");
    return v;
}

// Block = (row, seg). 1024 threads = 32 warps; warp span 1024 elems; lane owns
// 4 consecutive elems x 8 iters. flips read once (bit-packed into 1 register).
__global__ __launch_bounds__(1024, 1)
void SignStickyPhaseReconstructor_kernel(const float* __restrict__ edc,
                                         const int*   __restrict__ flips,
                                         float*       __restrict__ out)
{
    const int N    = 131072;           // outputs per row (T-1)
    const int TROW = 131073;           // edc elements per row
    const int SEGN = N / SEGS;         // 32768 outputs per block

    const int row  = blockIdx.x >> 2;
    const int seg  = blockIdx.x & 3;
    const int lane = threadIdx.x & 31;
    const int w    = threadIdx.x >> 5;
    const unsigned lmask = (1u << lane) - 1u;

    const int4*  flips4 = (const int4*)(flips + (long long)row * N);
    const float* erow   = edc + (long long)row * TROW;
    float4*      out4   = (float4*)(out + (long long)row * N);

    const int warpBase = seg * SEGN + w * 1024;   // row-relative

    // ---------------- Pass 1: read flips once, build parity structure ----------------
    unsigned bitsStore = 0u;   // 32 flip bits (8 iters x 4)
    unsigned pfx = 0u;         // bit i = warp-local exclusive parity before this lane at iter i
    unsigned run = 0u;         // running warp parity

    #pragma unroll
    for (int i = 0; i < 8; i++) {
        const int t = warpBase + i * 128 + lane * 4;
        int4 fv = flips4[t >> 2];
        unsigned b0 = (unsigned)fv.x & 1u;
        unsigned b1 = (unsigned)fv.y & 1u;
        unsigned b2 = (unsigned)fv.z & 1u;
        unsigned b3 = (unsigned)fv.w & 1u;
        if (t == 0) b0 = 0u;                      // flips[:,0] is never applied
        unsigned g  = b0 | (b1 << 1) | (b2 << 2) | (b3 << 3);
        unsigned gp = b0 ^ b1 ^ b2 ^ b3;

        unsigned bal      = __ballot_sync(FULL_MASK, gp);
        unsigned laneExcl = (unsigned)__popc(bal & lmask) & 1u;
        pfx |= ((run ^ laneExcl) & 1u) << i;
        run ^= (unsigned)__popc(bal) & 1u;

        bitsStore |= g << (i * 4);
    }

    // ---------------- Block combine + decoupled lookback across segments ----------------
    __shared__ unsigned warpPar[32];
    __shared__ unsigned warpExcl[32];
    __shared__ unsigned sPrev;

    warpPar[w] = run;                             // all lanes write same value
    __syncthreads();
    if (w == 0) {
        unsigned p   = warpPar[lane];
        unsigned bal = __ballot_sync(FULL_MASK, p);
        warpExcl[lane] = (unsigned)__popc(bal & lmask) & 1u;
        if (lane == 0) {
            unsigned blockAgg = (unsigned)__popc(bal) & 1u;
            publish_flag(&g_flags[blockIdx.x], (int)(2u | blockAgg));
            // XOR aggregates of segments 0..seg-1 of this row (blockIdx.x - seg .. -1)
            unsigned prev = 0u;
            for (int pb = blockIdx.x - seg; pb < (int)blockIdx.x; pb++) {
                int v;
                do { v = read_flag(&g_flags[pb]); } while (!(v & 2));
                prev ^= (unsigned)v & 1u;
            }
            sPrev = prev;
        }
    }
    __syncthreads();
    const unsigned baseAll = warpExcl[w] ^ sPrev;

    // ---------------- Pass 2: stream edc, emit signed sqrt(diff) ----------------
    #pragma unroll
    for (int i = 0; i < 8; i++) {
        const int t = warpBase + i * 128 + lane * 4;

        unsigned g = (bitsStore >> (i * 4)) & 0xFu;
        unsigned incl = g;
        incl ^= incl << 1;
        incl ^= incl << 2;
        incl &= 0xFu;                             // inclusive prefix-XOR within the 4-group
        unsigned flipAll = (((baseAll ^ (pfx >> i)) & 1u) ? 0xFu : 0u);
        unsigned s = incl ^ flipAll;              // bit k set -> negative sign

        float e0 = erow[t];
        float e1 = erow[t + 1];
        float e2 = erow[t + 2];
        float e3 = erow[t + 3];
        float e4 = __shfl_down_sync(FULL_MASK, e0, 1);   // lane l+1's e0 == erow[t+4]
        if (lane == 31) e4 = erow[t + 4];                // span boundary, t+4 <= N < TROW

        float a0 = fast_sqrt(fmaxf(e0 - e1, 0.0f));
        float a1 = fast_sqrt(fmaxf(e1 - e2, 0.0f));
        float a2 = fast_sqrt(fmaxf(e2 - e3, 0.0f));
        float a3 = fast_sqrt(fmaxf(e3 - e4, 0.0f));

        float4 o;
        o.x = (s & 1u) ? -a0 : a0;
        o.y = (s & 2u) ? -a1 : a1;
        o.z = (s & 4u) ? -a2 : a2;
        o.w = (s & 8u) ? -a3 : a3;
        out4[t >> 2] = o;
    }
}

extern "C" void kernel_launch(void* const* d_in, const int* in_sizes, int n_in,
                              void* d_out, int out_size)
{
    const int B = 256, T = 131073;

    const float* edc;
    const int*   flips;
    if (in_sizes[0] == B * T) {
        edc   = (const float*)d_in[0];
        flips = (const int*)  d_in[1];
    } else {
        edc   = (const float*)d_in[1];
        flips = (const int*)  d_in[0];
    }
    float* out = (float*)d_out;

    init_flags_kernel<<<1, NBLK>>>();
    SignStickyPhaseReconstructor_kernel<<<NBLK, 1024>>>(edc, flips, out);
}

// round 3
// speedup vs baseline: 1.2004x; 1.2004x over previous
#include <cuda_runtime.h>
#include <cuda_bf16.h>

#define FULL_MASK 0xFFFFFFFFu

static __device__ __forceinline__ float fast_sqrt(float x) {
    float y;
    asm("sqrt.approx.f32 %0, %1;" : "=f"(y) : "f"(x));
    return y;
}

static __device__ __forceinline__ float apply_sign(float a, unsigned neg) {
    // neg in {0,1}: flip sign bit via XOR (single LOP3)
    return __uint_as_float(__float_as_uint(a) ^ (neg << 31));
}

// Pass 2 body specialized on the row's 16B misalignment O = (row*131073) & 3.
// Each lane loads two aligned quads covering e[t-O .. t-O+7] and statically
// selects e[t..t+4]. No shuffles, no boundary lanes, 8 L1 wavefronts/iter.
template <int O>
static __device__ __forceinline__ void pass2(const float4* __restrict__ e4all,
                                             int qbase, int warpBase, int lane,
                                             uint4 bits, unsigned pfx, unsigned baseAll,
                                             float4* __restrict__ out4)
{
    #pragma unroll
    for (int i = 0; i < 32; i++) {
        const int t = warpBase + i * 128 + lane * 4;
        const int q = qbase + (t >> 2);
        float4 a = e4all[q];
        float4 b = e4all[q + 1];

        float e0, e1, e2, e3, e4;
        if (O == 0)      { e0 = a.x; e1 = a.y; e2 = a.z; e3 = a.w; e4 = b.x; }
        else if (O == 1) { e0 = a.y; e1 = a.z; e2 = a.w; e3 = b.x; e4 = b.y; }
        else if (O == 2) { e0 = a.z; e1 = a.w; e2 = b.x; e3 = b.y; e4 = b.z; }
        else             { e0 = a.w; e1 = b.x; e2 = b.y; e3 = b.z; e4 = b.w; }

        unsigned word = (i < 8) ? bits.x : (i < 16) ? bits.y : (i < 24) ? bits.z : bits.w;
        unsigned g = (word >> ((i & 7) * 4)) & 0xFu;
        unsigned incl = g;
        incl ^= incl << 1;
        incl ^= incl << 2;                          // inclusive prefix-XOR within the 4-group
        unsigned flipAll = (((baseAll ^ (pfx >> i)) & 1u) ? 0xFu : 0u);
        unsigned s = (incl ^ flipAll) & 0xFu;       // bit k set -> negative sign

        float a0 = fast_sqrt(fmaxf(e0 - e1, 0.0f));
        float a1 = fast_sqrt(fmaxf(e1 - e2, 0.0f));
        float a2 = fast_sqrt(fmaxf(e2 - e3, 0.0f));
        float a3 = fast_sqrt(fmaxf(e3 - e4, 0.0f));

        float4 o;
        o.x = apply_sign(a0,  s       & 1u);
        o.y = apply_sign(a1, (s >> 1) & 1u);
        o.z = apply_sign(a2, (s >> 2) & 1u);
        o.w = apply_sign(a3, (s >> 3) & 1u);
        out4[t >> 2] = o;
    }
}

// One block per row (B=256). 1024 threads = 32 warps; warp span 4096;
// lane owns 4 consecutive elems x 32 iters. flips read from HBM exactly once.
__global__ __launch_bounds__(1024, 1)
void SignStickyPhaseReconstructor_kernel(const float* __restrict__ edc,
                                         const int*   __restrict__ flips,
                                         float*       __restrict__ out)
{
    const int N    = 131072;   // outputs per row (T-1)
    const int TROW = 131073;   // edc elements per row

    const int row  = blockIdx.x;
    const int lane = threadIdx.x & 31;
    const int w    = threadIdx.x >> 5;
    const unsigned lmask = (1u << lane) - 1u;

    const int4*  flips4 = (const int4*)(flips + row * N);   // row*N < 2^31
    float4*      out4   = (float4*)(out + row * N);
    const int rowBase   = row * TROW;
    const int o         = rowBase & 3;                      // = row & 3
    const int qbase     = (rowBase - o) >> 2;               // aligned quad index of row start
    const float4* e4all = (const float4*)edc;

    const int warpBase = w * 4096;

    // ---------------- Pass 1: read flips once, build parity structure ----------------
    uint4 bits = make_uint4(0u, 0u, 0u, 0u);   // 128 flip bits per lane
    unsigned pfx = 0u;   // bit i = warp-local exclusive parity before this lane at iter i
    unsigned run = 0u;   // running warp parity across iterations

    #pragma unroll
    for (int i = 0; i < 32; i++) {
        const int t = warpBase + i * 128 + lane * 4;
        int4 fv = flips4[t >> 2];
        unsigned b0 = (unsigned)fv.x & 1u;
        unsigned b1 = (unsigned)fv.y & 1u;
        unsigned b2 = (unsigned)fv.z & 1u;
        unsigned b3 = (unsigned)fv.w & 1u;
        if (t == 0) b0 = 0u;                               // flips[:,0] is never applied
        unsigned g  = b0 | (b1 << 1) | (b2 << 2) | (b3 << 3);
        unsigned gp = b0 ^ b1 ^ b2 ^ b3;

        unsigned bal      = __ballot_sync(FULL_MASK, gp);
        unsigned laneExcl = (unsigned)__popc(bal & lmask) & 1u;
        pfx |= ((run ^ laneExcl) & 1u) << i;
        run ^= (unsigned)__popc(bal) & 1u;

        unsigned add = g << ((i & 7) * 4);
        if (i < 8)       bits.x |= add;
        else if (i < 16) bits.y |= add;
        else if (i < 24) bits.z |= add;
        else             bits.w |= add;
    }

    // ---------------- Block combine: XOR-scan of 32 warp parities ----------------
    __shared__ unsigned warpPar[32];
    __shared__ unsigned warpExcl[32];
    if (lane == 0) warpPar[w] = run;
    __syncthreads();
    if (w == 0) {
        unsigned p   = warpPar[lane];
        unsigned bal = __ballot_sync(FULL_MASK, p);
        warpExcl[lane] = (unsigned)__popc(bal & lmask) & 1u;
    }
    __syncthreads();
    const unsigned baseAll = warpExcl[w];

    // ---------------- Pass 2: uniform dispatch on row misalignment ----------------
    switch (o) {
        case 0: pass2<0>(e4all, qbase, warpBase, lane, bits, pfx, baseAll, out4); break;
        case 1: pass2<1>(e4all, qbase, warpBase, lane, bits, pfx, baseAll, out4); break;
        case 2: pass2<2>(e4all, qbase, warpBase, lane, bits, pfx, baseAll, out4); break;
        default: pass2<3>(e4all, qbase, warpBase, lane, bits, pfx, baseAll, out4); break;
    }
}

extern "C" void kernel_launch(void* const* d_in, const int* in_sizes, int n_in,
                              void* d_out, int out_size)
{
    const int B = 256, T = 131073;

    const float* edc;
    const int*   flips;
    if (in_sizes[0] == B * T) {
        edc   = (const float*)d_in[0];
        flips = (const int*)  d_in[1];
    } else {
        edc   = (const float*)d_in[1];
        flips = (const int*)  d_in[0];
    }
    float* out = (float*)d_out;

    SignStickyPhaseReconstructor_kernel<<<B, 1024>>>(edc, flips, out);
}